// round 3
// baseline (speedup 1.0000x reference)
#include <cuda_runtime.h>
#include <cstdint>

// Problem shape (fixed by the dataset): B=512, S=1024, T=64
#define Bn 512
#define Sn 1024
#define Tn 64

typedef unsigned long long u64;

__device__ float g_z[Bn];
__device__ float g_sc[Bn];

__device__ __forceinline__ u64 ffma2(u64 a, u64 b, u64 c) {
    u64 d;
    asm("fma.rn.f32x2 %0, %1, %2, %3;" : "=l"(d) : "l"(a), "l"(b), "l"(c));
    return d;
}
__device__ __forceinline__ u64 fadd2(u64 a, u64 b) {
    u64 d;
    asm("add.rn.f32x2 %0, %1, %2;" : "=l"(d) : "l"(a), "l"(b));
    return d;
}
__device__ __forceinline__ u64 fmul2(u64 a, u64 b) {
    u64 d;
    asm("mul.rn.f32x2 %0, %1, %2;" : "=l"(d) : "l"(a), "l"(b));
    return d;
}
__device__ __forceinline__ u64 pk2(float a, float b) {
    u64 d;
    asm("mov.b64 %0, {%1,%2};" : "=l"(d) : "f"(a), "f"(b));
    return d;
}
__device__ __forceinline__ float2 upk(u64 p) {
    float2 r;
    asm("mov.b64 {%0,%1}, %2;" : "=f"(r.x), "=f"(r.y) : "l"(p));
    return r;
}

// ---------------------------------------------------------------------------
// Forward recursion, linear domain:
//   s_{t+1}[j] = (sum_i s_t[i] * E[i][j]) * exp(e_t[j]),  E = exp(trans)
// Block = 128 threads = 4 warps, one batch.
//   thread (q = warp, c = lane): partial over i in [16q,16q+16) for columns
//   (2c, 2c+1). Quarter partials combined via smem; warp 0 owns the epilogue
//   (emission multiply, mask blend, power-of-2 renorm, publish s).
// ---------------------------------------------------------------------------
__global__ __launch_bounds__(128) void crf_forward(
    const float* __restrict__ em,    // [B, S, T]
    const float* __restrict__ mask,  // [B, S]
    const float* __restrict__ tr)    // [T, T]
{
    const int b = blockIdx.x;
    const int tid = threadIdx.x;
    const int q = tid >> 5;    // i-quarter / warp id
    const int c = tid & 31;    // column-pair index: cols 2c, 2c+1

    __shared__ __align__(16) float sbuf[Tn];   // current s vector
    __shared__ u64  part[3][32];               // quarter partials (warps 1-3)
    __shared__ float mrow[Sn];                 // mask row

    for (int i = tid; i < Sn; i += 128) mrow[i] = mask[b * Sn + i];

    // E register tiles: E0[ip] = (E[i0][2c], E[i0+1][2c]), E1 for col 2c+1
    u64 E0[8], E1[8];
#pragma unroll
    for (int ip = 0; ip < 8; ip++) {
        int i0 = q * 16 + 2 * ip;
        E0[ip] = pk2(__expf(tr[i0 * Tn + 2 * c]),
                     __expf(tr[(i0 + 1) * Tn + 2 * c]));
        E1[ip] = pk2(__expf(tr[i0 * Tn + 2 * c + 1]),
                     __expf(tr[(i0 + 1) * Tn + 2 * c + 1]));
    }

    if (tid < 32) ((u64*)sbuf)[tid] = pk2(1.0f, 1.0f);

    // Warp-0 emission pipeline: raw loaded 8 steps ahead, exp'd 4 steps ahead.
    const float2* ep = (const float2*)(em + (size_t)b * Sn * Tn) + c;
    float2 eraw[8];
    u64    fbuf[8];
    u64    s_old = pk2(1.0f, 1.0f);
    int    offk  = 0;
    if (q == 0) {
#pragma unroll
        for (int d = 0; d < 8; d++) eraw[d] = __ldg(ep + d * 32);
#pragma unroll
        for (int d = 0; d < 4; d++)
            fbuf[d] = pk2(__expf(eraw[d].x), __expf(eraw[d].y));
    }
    __syncthreads();

    for (int tb = 0; tb < Sn; tb += 8) {
#pragma unroll
        for (int u = 0; u < 8; u++) {
            const int t = tb + u;

            // ---- phase 1: quarter-partial matvec (all warps) ----
            const u64* sv = (const u64*)sbuf;
            u64 a0 = 0ull, a1 = 0ull, b0 = 0ull, b1 = 0ull;
#pragma unroll
            for (int ip = 0; ip < 8; ip += 2) {
                u64 s0 = sv[q * 8 + ip];
                u64 s1 = sv[q * 8 + ip + 1];
                a0 = ffma2(s0, E0[ip], a0);
                b0 = ffma2(s0, E1[ip], b0);
                a1 = ffma2(s1, E0[ip + 1], a1);
                b1 = ffma2(s1, E1[ip + 1], b1);
            }
            float2 pa = upk(fadd2(a0, a1));
            float2 pb = upk(fadd2(b0, b1));
            u64 mine = pk2(pa.x + pa.y, pb.x + pb.y);
            if (q != 0) part[q - 1][c] = mine;

            // warp 0: off-chain emission pipeline (exp 4 ahead, load 8 ahead)
            if (q == 0) {
                const int ue = (u + 4) & 7;
                fbuf[ue] = pk2(__expf(eraw[ue].x), __expf(eraw[ue].y));
                if (t + 8 < Sn) eraw[u] = __ldg(ep + (size_t)(t + 8) * 32);
            }
            __syncthreads();

            // ---- phase 2: combine + epilogue (warp 0 only) ----
            if (q == 0) {
                u64 tot = fadd2(fadd2(mine, part[0][c]),
                                fadd2(part[1][c], part[2][c]));
                u64 qf  = fmul2(tot, fbuf[u]);
                float m  = mrow[t];
                float om = 1.0f - m;
                u64 sn = ffma2(pk2(om, om), s_old, fmul2(pk2(m, m), qf));
                if (u == 7) {
                    // renorm by 2^-ke, ke from exponent of s[0] (lane 0)
                    float s00 = __shfl_sync(0xffffffffu, upk(sn).x, 0);
                    int ke = ((__float_as_int(s00) >> 23) & 0xff) - 127;
                    offk += ke;
                    float sc = __int_as_float((127 - ke) << 23);
                    sn = fmul2(sn, pk2(sc, sc));
                }
                s_old = sn;
                ((u64*)sbuf)[c] = sn;
            }
            __syncthreads();
        }
    }

    // z[b] = offk*ln2 + log(sum_j s[j]) — warp 0 holds final s pairs
    if (q == 0) {
        float2 sp = upk(s_old);
        float x = sp.x + sp.y;
#pragma unroll
        for (int o = 16; o; o >>= 1)
            x += __shfl_xor_sync(0xffffffffu, x, o);
        if (c == 0) {
            double z = (double)offk * 0.6931471805599453
                     + (double)logf(x);
            g_z[b] = (float)z;
        }
    }
}

// ---------------------------------------------------------------------------
// Gold path scores
// ---------------------------------------------------------------------------
__global__ __launch_bounds__(256) void crf_gold(
    const float* __restrict__ em,
    const int*   __restrict__ tags,
    const float* __restrict__ mask,
    const float* __restrict__ tr)
{
    __shared__ float red[256];
    const int b   = blockIdx.x;
    const int tid = threadIdx.x;

    const int* tg = tags + b * Sn;
    float acc = 0.0f;
    for (int s = 1 + tid; s < Sn; s += 256) {
        int   t1  = tg[s];
        int   t0  = tg[s - 1];
        float mt  = mask[b * Sn + s];
        float emv = __ldg(em + (size_t)b * Sn * Tn + (size_t)s * Tn + t1);
        float trv = tr[t0 * Tn + t1];
        acc += (emv + trv) * mt;
    }
    red[tid] = acc;
    __syncthreads();
    for (int st = 128; st; st >>= 1) {
        if (tid < st) red[tid] += red[tid + st];
        __syncthreads();
    }
    if (tid == 0) g_sc[b] = red[0];
}

// ---------------------------------------------------------------------------
// out = -mean(z - score)
// ---------------------------------------------------------------------------
__global__ __launch_bounds__(Bn) void crf_final(float* __restrict__ out)
{
    __shared__ float red[Bn];
    const int tid = threadIdx.x;
    red[tid] = g_z[tid] - g_sc[tid];
    __syncthreads();
    for (int st = Bn / 2; st; st >>= 1) {
        if (tid < st) red[tid] += red[tid + st];
        __syncthreads();
    }
    if (tid == 0) out[0] = -red[0] / (float)Bn;
}

extern "C" void kernel_launch(void* const* d_in, const int* in_sizes, int n_in,
                              void* d_out, int out_size)
{
    const float* em   = (const float*)d_in[0];  // emissions [B,S,T] f32
    const int*   tags = (const int*)  d_in[1];  // tags [B,S] i32
    const float* mask = (const float*)d_in[2];  // mask [B,S] f32
    const float* tr   = (const float*)d_in[3];  // transitions [T,T] f32

    crf_forward<<<Bn, 128>>>(em, mask, tr);
    crf_gold<<<Bn, 256>>>(em, tags, mask, tr);
    crf_final<<<1, Bn>>>((float*)d_out);
}

// round 4
// speedup vs baseline: 2.5242x; 2.5242x over previous
#include <cuda_runtime.h>
#include <cstdint>

// Problem shape (fixed by the dataset): B=512, S=1024, T=64
#define Bn 512
#define Sn 1024
#define Tn 64
#define WPB 4   // warps per block; one batch per warp (warp w -> SMSP w)

typedef unsigned long long u64;

__device__ float g_z[Bn];
__device__ float g_sc[Bn];

__device__ __forceinline__ u64 ffma2(u64 a, u64 b, u64 c) {
    u64 d;
    asm("fma.rn.f32x2 %0, %1, %2, %3;" : "=l"(d) : "l"(a), "l"(b), "l"(c));
    return d;
}
__device__ __forceinline__ u64 fadd2(u64 a, u64 b) {
    u64 d;
    asm("add.rn.f32x2 %0, %1, %2;" : "=l"(d) : "l"(a), "l"(b));
    return d;
}
__device__ __forceinline__ u64 fmul2(u64 a, u64 b) {
    u64 d;
    asm("mul.rn.f32x2 %0, %1, %2;" : "=l"(d) : "l"(a), "l"(b));
    return d;
}
__device__ __forceinline__ u64 pk2(float a, float b) {
    u64 d;
    asm("mov.b64 %0, {%1,%2};" : "=l"(d) : "f"(a), "f"(b));
    return d;
}
__device__ __forceinline__ float2 upk(u64 p) {
    float2 r;
    asm("mov.b64 {%0,%1}, %2;" : "=f"(r.x), "=f"(r.y) : "l"(p));
    return r;
}

// ---------------------------------------------------------------------------
// Forward recursion, linear domain, ONE WARP PER BATCH (no block barriers):
//   s_{t+1}[j] = (sum_i s_t[i] * E[i][j]) * exp(e_t[j]),  E = exp(trans)
// Thread c owns the adjacent column pair (2c, 2c+1); each broadcast s-pair
// read from warp-private smem feeds both columns (half the crossbar traffic
// of the 1-col/thread layout). Renorm every 8 steps by a power of two taken
// from the exponent bits of s[0] (uniform across lanes).
// ---------------------------------------------------------------------------
__global__ __launch_bounds__(32 * WPB, 1) void crf_forward(
    const float* __restrict__ em,    // [B, S, T]
    const float* __restrict__ mask,  // [B, S]
    const float* __restrict__ tr)    // [T, T]
{
    const int w = threadIdx.x >> 5;   // warp id = batch-within-block
    const int c = threadIdx.x & 31;   // column pair: cols 2c, 2c+1
    const int b = blockIdx.x * WPB + w;

    __shared__ __align__(16) u64 sbuf[WPB][2][32];  // double-buffered s pairs
    __shared__ float2 mrow[WPB][Sn];                // (m, 1-m) per step

    // Stage mask row (warp-private region, no block sync needed)
    for (int i = c; i < Sn; i += 32) {
        float m = mask[b * Sn + i];
        mrow[w][i] = make_float2(m, 1.0f - m);
    }

    // E register tiles for this thread's two columns:
    //   EA[p] = (E[2p][2c],   E[2p+1][2c])
    //   EB[p] = (E[2p][2c+1], E[2p+1][2c+1])
    u64 EA[32], EB[32];
#pragma unroll
    for (int p = 0; p < 32; p++) {
        EA[p] = pk2(__expf(tr[(2 * p) * Tn + 2 * c]),
                    __expf(tr[(2 * p + 1) * Tn + 2 * c]));
        EB[p] = pk2(__expf(tr[(2 * p) * Tn + 2 * c + 1]),
                    __expf(tr[(2 * p + 1) * Tn + 2 * c + 1]));
    }

    // Emission pipeline: raw float2 loaded 8 steps ahead, exp'd 2 steps ahead
    const float2* ep = (const float2*)(em + (size_t)b * Sn * Tn) + c;
    float2 eraw[8];
    u64    fbuf[4];
#pragma unroll
    for (int d = 0; d < 8; d++) eraw[d] = __ldg(ep + d * 32);
#pragma unroll
    for (int d = 0; d < 2; d++)
        fbuf[d] = pk2(__expf(eraw[d].x), __expf(eraw[d].y));

    u64 s    = pk2(1.0f, 1.0f);
    int offk = 0;
    __syncwarp();

    for (int tb = 0; tb < Sn; tb += 8) {
#pragma unroll
        for (int u = 0; u < 8; u++) {
            const int t   = tb + u;
            const int par = u & 1;

            // publish own pair; warp-local sync
            sbuf[w][par][c] = s;
            __syncwarp();

            // exp pipeline refill (independent of s-chain): exp 2 ahead,
            // reload raw slot 8 ahead
            fbuf[(u + 2) & 3] =
                pk2(__expf(eraw[(u + 2) & 7].x), __expf(eraw[(u + 2) & 7].y));
            if (t + 8 < Sn) eraw[u] = __ldg(ep + (size_t)(t + 8) * 32);

            // matvec for both columns: 16 LDS.128 (v2.u64), 64 FFMA2
            const u64* sv = &sbuf[w][par][0];
            u64 a0 = 0, a1 = 0, a2 = 0, a3 = 0;
            u64 b0 = 0, b1 = 0, b2 = 0, b3 = 0;
            u64 v0pair;
#pragma unroll
            for (int p = 0; p < 32; p += 4) {
                ulonglong2 x = *(const ulonglong2*)&sv[p];
                ulonglong2 y = *(const ulonglong2*)&sv[p + 2];
                if (p == 0) v0pair = x.x;
                a0 = ffma2(x.x, EA[p + 0], a0);
                b0 = ffma2(x.x, EB[p + 0], b0);
                a1 = ffma2(x.y, EA[p + 1], a1);
                b1 = ffma2(x.y, EB[p + 1], b1);
                a2 = ffma2(y.x, EA[p + 2], a2);
                b2 = ffma2(y.x, EB[p + 2], b2);
                a3 = ffma2(y.y, EA[p + 3], a3);
                b3 = ffma2(y.y, EB[p + 3], b3);
            }
            u64 sa = fadd2(fadd2(a0, a1), fadd2(a2, a3));
            u64 sb = fadd2(fadd2(b0, b1), fadd2(b2, b3));
            float2 fa = upk(sa), fb = upk(sb);
            u64 qf = fmul2(pk2(fa.x + fa.y, fb.x + fb.y), fbuf[u & 3]);

            // masked blend: s = m*qf + (1-m)*s
            float2 mm = mrow[w][t];
            u64 sn = ffma2(pk2(mm.y, mm.y), s, fmul2(pk2(mm.x, mm.x), qf));

            // renorm every 8 steps by 2^-ke, ke from exponent of s[0]
            // (v0pair.x is this step's pre-update s[0], uniform across lanes)
            if (u == 7) {
                int ke = ((__float_as_int(upk(v0pair).x) >> 23) & 0xff) - 127;
                offk += ke;
                float sc = __int_as_float((127 - ke) << 23);
                sn = fmul2(sn, pk2(sc, sc));
            }
            s = sn;
        }
    }

    // z[b] = offk*ln2 + log(sum_j s[j])
    float2 sp = upk(s);
    float x = sp.x + sp.y;
#pragma unroll
    for (int o = 16; o; o >>= 1)
        x += __shfl_xor_sync(0xffffffffu, x, o);
    if (c == 0) {
        double z = (double)offk * 0.6931471805599453 + (double)logf(x);
        g_z[b] = (float)z;
    }
}

// ---------------------------------------------------------------------------
// Gold path scores
// ---------------------------------------------------------------------------
__global__ __launch_bounds__(256) void crf_gold(
    const float* __restrict__ em,
    const int*   __restrict__ tags,
    const float* __restrict__ mask,
    const float* __restrict__ tr)
{
    __shared__ float red[256];
    const int b   = blockIdx.x;
    const int tid = threadIdx.x;

    const int* tg = tags + b * Sn;
    float acc = 0.0f;
    for (int s = 1 + tid; s < Sn; s += 256) {
        int   t1  = tg[s];
        int   t0  = tg[s - 1];
        float mt  = mask[b * Sn + s];
        float emv = __ldg(em + (size_t)b * Sn * Tn + (size_t)s * Tn + t1);
        float trv = tr[t0 * Tn + t1];
        acc += (emv + trv) * mt;
    }
    red[tid] = acc;
    __syncthreads();
    for (int st = 128; st; st >>= 1) {
        if (tid < st) red[tid] += red[tid + st];
        __syncthreads();
    }
    if (tid == 0) g_sc[b] = red[0];
}

// ---------------------------------------------------------------------------
// out = -mean(z - score)
// ---------------------------------------------------------------------------
__global__ __launch_bounds__(Bn) void crf_final(float* __restrict__ out)
{
    __shared__ float red[Bn];
    const int tid = threadIdx.x;
    red[tid] = g_z[tid] - g_sc[tid];
    __syncthreads();
    for (int st = Bn / 2; st; st >>= 1) {
        if (tid < st) red[tid] += red[tid + st];
        __syncthreads();
    }
    if (tid == 0) out[0] = -red[0] / (float)Bn;
}

extern "C" void kernel_launch(void* const* d_in, const int* in_sizes, int n_in,
                              void* d_out, int out_size)
{
    const float* em   = (const float*)d_in[0];  // emissions [B,S,T] f32
    const int*   tags = (const int*)  d_in[1];  // tags [B,S] i32
    const float* mask = (const float*)d_in[2];  // mask [B,S] f32
    const float* tr   = (const float*)d_in[3];  // transitions [T,T] f32

    crf_forward<<<Bn / WPB, 32 * WPB>>>(em, mask, tr);
    crf_gold<<<Bn, 256>>>(em, tags, mask, tr);
    crf_final<<<1, Bn>>>((float*)d_out);
}